// round 12
// baseline (speedup 1.0000x reference)
#include <cuda_runtime.h>
#include <cuda_fp16.h>
#include <math.h>
#include <stdint.h>

// Problem constants
constexpr int Bc = 4, Lc = 2048, Dc = 512;
constexpr int MR = Bc * Lc;       // 8192

// ---------------------------------------------------------------------------
// Device scratch (no allocations allowed)
// ---------------------------------------------------------------------------
__device__ __half g_xh [(size_t)MR * 3072];
__device__ __half g_wqh[(size_t)2048 * 3072];
__device__ __half g_woh[(size_t)1024 * 1024];
__device__ __half g_q  [(size_t)MR * 512];
__device__ __half g_k  [(size_t)MR * 512];
__device__ __half g_v  [(size_t)MR * 1024];
__device__ __half g_attnh[(size_t)MR * Lc];
__device__ float  g_partial[(size_t)MR * 16];
__device__ __half g_oh [(size_t)MR * 1024];
// dependency counters (block-granular)
__device__ int g_cq[64];   // qk tiles per m-block        (==8 when q,k rows ready)
__device__ int g_cv[32];   // v tiles per (bz, n-block)   (==16 when V cols ready)
__device__ int g_cs[64];   // score tiles per (bz,m-blk)  (==16 when attnh rows + partials ready)
__device__ int g_ca[64];   // av tiles per m-block        (==8 when oh rows ready)

// ---------------------------------------------------------------------------
// PTX helpers
// ---------------------------------------------------------------------------
__device__ __forceinline__ uint32_t smem_u32(const void* p) {
    uint32_t a;
    asm("{ .reg .u64 t; cvta.to.shared.u64 t, %1; cvt.u32.u64 %0, t; }" : "=r"(a) : "l"(p));
    return a;
}
__device__ __forceinline__ void cp_async16(uint32_t saddr, const void* gaddr) {
    asm volatile("cp.async.cg.shared.global [%0], [%1], 16;" :: "r"(saddr), "l"(gaddr));
}
#define CP_COMMIT() asm volatile("cp.async.commit_group;" ::: "memory")
#define CP_WAIT(N)  asm volatile("cp.async.wait_group %0;" :: "n"(N) : "memory")

__device__ __forceinline__ void ldm_x4(uint32_t* r, uint32_t addr) {
    asm volatile("ldmatrix.sync.aligned.m8n8.x4.shared.b16 {%0,%1,%2,%3}, [%4];"
                 : "=r"(r[0]), "=r"(r[1]), "=r"(r[2]), "=r"(r[3]) : "r"(addr));
}
__device__ __forceinline__ void ldm_x4_trans(uint32_t* r, uint32_t addr) {
    asm volatile("ldmatrix.sync.aligned.m8n8.x4.trans.shared.b16 {%0,%1,%2,%3}, [%4];"
                 : "=r"(r[0]), "=r"(r[1]), "=r"(r[2]), "=r"(r[3]) : "r"(addr));
}
__device__ __forceinline__ void mma16816(float* c, const uint32_t* a,
                                         uint32_t b0, uint32_t b1) {
    asm volatile(
        "mma.sync.aligned.m16n8k16.row.col.f32.f16.f16.f32 "
        "{%0,%1,%2,%3}, {%4,%5,%6,%7}, {%8,%9}, {%0,%1,%2,%3};"
        : "+f"(c[0]), "+f"(c[1]), "+f"(c[2]), "+f"(c[3])
        : "r"(a[0]), "r"(a[1]), "r"(a[2]), "r"(a[3]), "r"(b0), "r"(b1));
}

// ---------------------------------------------------------------------------
// Tiling constants
// ---------------------------------------------------------------------------
constexpr int ROWH = 72;
constexpr int VROW = 136;
constexpr int OP_TILE = 128 * ROWH * 2;       // 18432 B
constexpr int STAGE = 2 * OP_TILE;            // 36864 B
constexpr int SMEM_TOTAL = 2 * STAGE;         // 73728 B

// ---------------------------------------------------------------------------
// Megakernel: all four GEMMs, dependency-counted.
// bid  0..511  : qkv qk-half   (bm64 = bid>>3, bn8 = bid&7; n in [0,1024))
// bid 512..1023: qkv v-half    (n in [1024,2048) -> g_v cols 0..1023)
// bid 1024..2047: scores+exp   (b = bz*256 + bm16*16 + xt)
// bid 2048..2559: attn@V       (b = (bz*16+bm16)*8 + bn8)
// bid 2560..3071: out proj     (b = bm64*8 + bn8)
// ---------------------------------------------------------------------------
__global__ void __launch_bounds__(128, 3) k_mega(const float* __restrict__ bqkv,
                                                 const int* __restrict__ pad,
                                                 const float* __restrict__ bout,
                                                 float* __restrict__ outf)
{
    extern __shared__ char smem[];
    const uint32_t sb = smem_u32(smem);
    const int tid = threadIdx.x, wid = tid >> 5, lane = tid & 31;
    const int wm = wid & 1, wn = wid >> 1;

    const int bid = blockIdx.x;
    int job, bm, bn, bz = 0, xt = 0;
    const __half* A; const __half* B; int K, lda, ldb;
    bool trv = false;

    if (bid < 512) {               // qk
        job = 0;
        bn = (bid & 7) * 128; bm = (bid >> 3) * 128;
        A = g_xh; B = g_wqh; K = 3072; lda = 3072; ldb = 3072;
    } else if (bid < 1024) {       // v
        job = 1;
        const int b = bid - 512;
        bn = 1024 + (b & 7) * 128; bm = (b >> 3) * 128;
        A = g_xh; B = g_wqh; K = 3072; lda = 3072; ldb = 3072;
    } else if (bid < 2048) {       // scores
        job = 2;
        const int b = bid - 1024;
        bz = b >> 8; const int r = b & 255;
        const int bm16 = r >> 4; xt = r & 15;
        bm = bm16 * 128; bn = xt * 128;
        A = g_q + (size_t)bz * 2048 * 512; B = g_k + (size_t)bz * 2048 * 512;
        K = 512; lda = 512; ldb = 512;
        if (tid == 0) {
            int* c1 = &g_cq[bz * 16 + bm16];
            int* c2 = &g_cq[bz * 16 + xt];
            while (atomicAdd(c1, 0) < 8) __nanosleep(100);
            while (atomicAdd(c2, 0) < 8) __nanosleep(100);
        }
        __syncthreads(); __threadfence();
    } else if (bid < 2560) {       // av
        job = 3; trv = true;
        const int b = bid - 2048;
        const int blk = b >> 3;    // bz*16+bm16
        const int bn8 = b & 7;
        bz = blk >> 4; bm = (blk & 15) * 128; bn = bn8 * 128;
        A = g_attnh + (size_t)bz * 2048 * 2048; B = g_v + (size_t)bz * 2048 * 1024;
        K = 2048; lda = 2048; ldb = 1024;
        if (tid == 0) {
            int* c1 = &g_cs[blk];
            int* c2 = &g_cv[bz * 8 + bn8];
            while (atomicAdd(c1, 0) < 16) __nanosleep(100);
            while (atomicAdd(c2, 0) < 16) __nanosleep(100);
        }
        __syncthreads(); __threadfence();
    } else {                       // out
        job = 4;
        const int b = bid - 2560;
        const int bm64 = b >> 3;
        bm = bm64 * 128; bn = (b & 7) * 128;
        A = g_oh; B = g_woh; K = 1024; lda = 1024; ldb = 1024;
        if (tid == 0) {
            int* c1 = &g_ca[bm64];
            while (atomicAdd(c1, 0) < 8) __nanosleep(100);
        }
        __syncthreads(); __threadfence();
    }

    auto load_tile = [&](int s, int k0) {
        const uint32_t base = sb + s * STAGE;
#pragma unroll
        for (int i = 0; i < 8; i++) {
            const int j = tid + i * 128;
            const int r = j >> 3, c = (j & 7) * 8;
            cp_async16(base + (r * ROWH + c) * 2,
                       A + (size_t)(bm + r) * lda + k0 + c);
            if (trv) {
                const int rv = j >> 4, cv = (j & 15) * 8;
                cp_async16(base + OP_TILE + (rv * VROW + cv) * 2,
                           B + (size_t)(k0 + rv) * ldb + bn + cv);
            } else {
                cp_async16(base + OP_TILE + (r * ROWH + c) * 2,
                           B + (size_t)(bn + r) * ldb + k0 + c);
            }
        }
    };

    float acc[4][8][4] = {};
    uint32_t fa[2][4][4], fb[2][4][4];

    const int ar = wm * 64 + (lane & 15);
    const int br = wn * 64 + (lane & 7) + ((lane >> 4) << 3);
    const int acolo = (lane >> 4) * 8;
    const int bcolo = ((lane >> 3) & 1) * 8;
    const int bk_l = ((lane >> 3) & 1) * 8 + (lane & 7);
    const int bn_l = ((lane >> 4) & 1) * 8;

    load_tile(0, 0);
    CP_COMMIT();

    const int NC = K >> 6;
    for (int ct = 0; ct < NC; ct++) {
        if (ct + 1 < NC) { load_tile((ct + 1) & 1, (ct + 1) * 64); CP_COMMIT(); CP_WAIT(1); }
        else             { CP_WAIT(0); }
        __syncthreads();

        const uint32_t as = sb + (ct & 1) * STAGE;
        const uint32_t bs = as + OP_TILE;

        auto ldfrag = [&](int buf, int ks) {
            const int acol = ks * 16 + acolo;
#pragma unroll
            for (int mt = 0; mt < 4; mt++)
                ldm_x4(fa[buf][mt], as + ((ar + mt * 16) * ROWH + acol) * 2);
            if (trv) {
                const int krow = ks * 16 + bk_l;
#pragma unroll
                for (int np = 0; np < 4; np++)
                    ldm_x4_trans(fb[buf][np],
                        bs + (krow * VROW + wn * 64 + np * 16 + bn_l) * 2);
            } else {
                const int bcol = ks * 16 + bcolo;
#pragma unroll
                for (int np = 0; np < 4; np++)
                    ldm_x4(fb[buf][np], bs + ((br + np * 16) * ROWH + bcol) * 2);
            }
        };

        ldfrag(0, 0);
#pragma unroll
        for (int ks = 0; ks < 4; ks++) {
            if (ks < 3) ldfrag((ks + 1) & 1, ks + 1);
            const int cb = ks & 1;
#pragma unroll
            for (int mt = 0; mt < 4; mt++)
#pragma unroll
                for (int nt = 0; nt < 8; nt++)
                    mma16816(acc[mt][nt], fa[cb][mt],
                             fb[cb][nt >> 1][(nt & 1) * 2],
                             fb[cb][nt >> 1][(nt & 1) * 2 + 1]);
        }
        __syncthreads();
    }

    // ---------------- epilogues ----------------
    const int g = lane >> 2, cc = lane & 3;

    if (job == 0) {                      // qk: write g_q / g_k
#pragma unroll
        for (int mt = 0; mt < 4; mt++) {
#pragma unroll
            for (int nt = 0; nt < 8; nt++) {
                const int n = bn + wn * 64 + nt * 8 + cc * 2;
                const int m1 = bm + wm * 64 + mt * 16 + g;
                const int m2 = m1 + 8;
                const float* v = acc[mt][nt];
                const int jb = n + (n >= 512 ? 512 : 0);
                const float b0 = bqkv[jb], b1 = bqkv[jb + 1];
                __half* d1; __half* d2;
                if (n < 512) { d1 = g_q + (size_t)m1*512 + n;     d2 = g_q + (size_t)m2*512 + n; }
                else         { d1 = g_k + (size_t)m1*512 + n-512; d2 = g_k + (size_t)m2*512 + n-512; }
                *(__half2*)d1 = __floats2half2_rn(v[0] + b0, v[1] + b1);
                *(__half2*)d2 = __floats2half2_rn(v[2] + b0, v[3] + b1);
            }
        }
        __threadfence(); __syncthreads();
        if (tid == 0) atomicAdd(&g_cq[bm >> 7], 1);
        return;
    }

    if (job == 1) {                      // v: write g_v
#pragma unroll
        for (int mt = 0; mt < 4; mt++) {
#pragma unroll
            for (int nt = 0; nt < 8; nt++) {
                const int n = bn + wn * 64 + nt * 8 + cc * 2;
                const int m1 = bm + wm * 64 + mt * 16 + g;
                const int m2 = m1 + 8;
                const float* v = acc[mt][nt];
                const float b0 = bqkv[n + 1024], b1 = bqkv[n + 1025];
                __half* d1 = g_v + (size_t)m1 * 1024 + n - 1024;
                __half* d2 = g_v + (size_t)m2 * 1024 + n - 1024;
                *(__half2*)d1 = __floats2half2_rn(v[0] + b0, v[1] + b1);
                *(__half2*)d2 = __floats2half2_rn(v[2] + b0, v[3] + b1);
            }
        }
        __threadfence(); __syncthreads();
        if (tid == 0) {
            const int bm64 = bm >> 7;
            atomicAdd(&g_cv[(bm64 >> 4) * 8 + ((bid - 512) & 7)], 1);
        }
        return;
    }

    if (job == 2) {                      // scores: exp + partial sums
        float (*psum)[128] = (float(*)[128])smem;   // reuse tile smem
        const float scale = 0.04419417382415922f;
        int2 pmv[8];
#pragma unroll
        for (int nt = 0; nt < 8; nt++)
            pmv[nt] = *(const int2*)(pad + (size_t)bz * 2048 + bn + wn * 64 + nt * 8 + cc * 2);

        float rs[4][2] = {};
#pragma unroll
        for (int mt = 0; mt < 4; mt++) {
#pragma unroll
            for (int nt = 0; nt < 8; nt++) {
                const int n = bn + wn * 64 + nt * 8 + cc * 2;
                const int m1 = bm + wm * 64 + mt * 16 + g;
                const int m2 = m1 + 8;
                const float* v = acc[mt][nt];
                const float p0 = pmv[nt].x ? 0.f : __expf(v[0] * scale);
                const float p1 = pmv[nt].y ? 0.f : __expf(v[1] * scale);
                const float p2 = pmv[nt].x ? 0.f : __expf(v[2] * scale);
                const float p3 = pmv[nt].y ? 0.f : __expf(v[3] * scale);
                __half* d1 = g_attnh + (size_t)(bz*2048 + m1) * 2048 + n;
                __half* d2 = g_attnh + (size_t)(bz*2048 + m2) * 2048 + n;
                *(__half2*)d1 = __floats2half2_rn(p0, p1);
                *(__half2*)d2 = __floats2half2_rn(p2, p3);
                rs[mt][0] += p0 + p1;
                rs[mt][1] += p2 + p3;
            }
        }
#pragma unroll
        for (int mt = 0; mt < 4; mt++) {
            rs[mt][0] += __shfl_xor_sync(0xFFFFFFFF, rs[mt][0], 1);
            rs[mt][0] += __shfl_xor_sync(0xFFFFFFFF, rs[mt][0], 2);
            rs[mt][1] += __shfl_xor_sync(0xFFFFFFFF, rs[mt][1], 1);
            rs[mt][1] += __shfl_xor_sync(0xFFFFFFFF, rs[mt][1], 2);
            if (cc == 0) {
                psum[wn][wm * 64 + mt * 16 + g]     = rs[mt][0];
                psum[wn][wm * 64 + mt * 16 + g + 8] = rs[mt][1];
            }
        }
        __syncthreads();
        if (tid < 128)
            g_partial[((size_t)bz * 2048 + bm + tid) * 16 + xt] =
                psum[0][tid] + psum[1][tid];
        __threadfence(); __syncthreads();
        if (tid == 0) atomicAdd(&g_cs[bz * 16 + (bm >> 7)], 1);
        return;
    }

    if (job == 3) {                      // av: inline rowsum + normalize -> g_oh
        float* sinv = (float*)smem;      // reuse tile smem
        if (tid < 128) {
            const float4* p = (const float4*)(g_partial + ((size_t)bz * 2048 + bm + tid) * 16);
            float4 a = p[0], b = p[1], c = p[2], d = p[3];
            const float s = ((a.x + a.y) + (a.z + a.w)) + ((b.x + b.y) + (b.z + b.w))
                          + ((c.x + c.y) + (c.z + c.w)) + ((d.x + d.y) + (d.z + d.w));
            sinv[tid] = 1.f / s;
        }
        __syncthreads();
#pragma unroll
        for (int mt = 0; mt < 4; mt++) {
#pragma unroll
            for (int nt = 0; nt < 8; nt++) {
                const int n = bn + wn * 64 + nt * 8 + cc * 2;
                const int l1 = wm * 64 + mt * 16 + g;
                const int m1 = bm + l1, m2 = m1 + 8;
                const float* v = acc[mt][nt];
                const float inv1 = sinv[l1], inv2 = sinv[l1 + 8];
                __half* d1 = g_oh + (size_t)(bz*2048 + m1) * 1024 + n;
                __half* d2 = g_oh + (size_t)(bz*2048 + m2) * 1024 + n;
                *(__half2*)d1 = __floats2half2_rn(v[0] * inv1, v[1] * inv1);
                *(__half2*)d2 = __floats2half2_rn(v[2] * inv2, v[3] * inv2);
            }
        }
        __threadfence(); __syncthreads();
        if (tid == 0) atomicAdd(&g_ca[bz * 16 + (bm >> 7)], 1);
        return;
    }

    // job == 4: out projection
#pragma unroll
    for (int mt = 0; mt < 4; mt++) {
#pragma unroll
        for (int nt = 0; nt < 8; nt++) {
            const int n = bn + wn * 64 + nt * 8 + cc * 2;
            const int m1 = bm + wm * 64 + mt * 16 + g;
            const int m2 = m1 + 8;
            const float* v = acc[mt][nt];
            const float b0 = bout[n], b1 = bout[n + 1];
            float* o1; float* o2;
            if (n < 512) { o1 = outf + (size_t)m1*512 + n;       o2 = outf + (size_t)m2*512 + n; }
            else         { o1 = outf + (size_t)MR*512 + (size_t)m1*512 + n-512;
                           o2 = outf + (size_t)MR*512 + (size_t)m2*512 + n-512; }
            *(float2*)o1 = make_float2(v[0] + b0, v[1] + b1);
            *(float2*)o2 = make_float2(v[2] + b0, v[3] + b1);
        }
    }
}

// ---------------------------------------------------------------------------
// Conversions (+ counter reset)
// ---------------------------------------------------------------------------
__global__ void __launch_bounds__(256) k_conv_x(
    const float* __restrict__ i0, const float* __restrict__ i1,
    const float* __restrict__ i2, const float* __restrict__ i3,
    const float* __restrict__ i4, const float* __restrict__ i5)
{
    const int m = blockIdx.x, t = threadIdx.x;
    if (m == 0) {   // reset dependency counters each replay
        if (t < 64)        g_cq[t] = 0;
        else if (t < 96)   g_cv[t - 64] = 0;
        else if (t < 160)  g_cs[t - 96] = 0;
        else if (t < 224)  g_ca[t - 160] = 0;
    }
    const float* ins[6] = {i0, i1, i2, i3, i4, i5};
    __half2* out = (__half2*)(g_xh + (size_t)m * 3072);
#pragma unroll
    for (int i = 0; i < 6; i++) {
        float2 v = ((const float2*)(ins[i] + (size_t)m * 512))[t];
        out[i * 256 + t] = __floats2half2_rn(v.x, v.y);
    }
}

__global__ void __launch_bounds__(256) k_conv_wq(const float* __restrict__ W)
{
    const int n = blockIdx.x, t = threadIdx.x;
    const int wrow = n + (n >= 512 ? 512 : 0) + (n >= 1024 ? 512 : 0);
    const float2* src = (const float2*)(W + (size_t)wrow * 3072);
    __half2* dst = (__half2*)(g_wqh + (size_t)n * 3072);
#pragma unroll
    for (int i = 0; i < 6; i++) {
        float2 v = src[t + i * 256];
        dst[t + i * 256] = __floats2half2_rn(v.x, v.y);
    }
}

__global__ void __launch_bounds__(256) k_conv_wo(const float* __restrict__ W)
{
    const int n = blockIdx.x, t = threadIdx.x;
    const float2* src = (const float2*)(W + (size_t)n * 1024);
    __half2* dst = (__half2*)(g_woh + (size_t)n * 1024);
#pragma unroll
    for (int i = 0; i < 2; i++) {
        float2 v = src[t + i * 256];
        dst[t + i * 256] = __floats2half2_rn(v.x, v.y);
    }
}

// ---------------------------------------------------------------------------
extern "C" void kernel_launch(void* const* d_in, const int* in_sizes, int n_in,
                              void* d_out, int out_size)
{
    const float* q_r = (const float*)d_in[0];
    const float* q_i = (const float*)d_in[1];
    const float* k_r = (const float*)d_in[2];
    const float* k_i = (const float*)d_in[3];
    const float* v_r = (const float*)d_in[4];
    const float* v_i = (const float*)d_in[5];
    const int* pad   = (const int*)d_in[6];
    const float* Wqkv = (const float*)d_in[7];
    const float* bqkv = (const float*)d_in[8];
    const float* Wout = (const float*)d_in[9];
    const float* bout = (const float*)d_in[10];
    float* out = (float*)d_out;

    cudaFuncSetAttribute(k_mega, cudaFuncAttributeMaxDynamicSharedMemorySize, SMEM_TOTAL);

    k_conv_x<<<MR, 256>>>(q_r, q_i, k_r, k_i, v_r, v_i);
    k_conv_wq<<<2048, 256>>>(Wqkv);
    k_conv_wo<<<1024, 256>>>(Wout);

    k_mega<<<3072, 128, SMEM_TOTAL>>>(bqkv, pad, bout, out);
}

// round 13
// speedup vs baseline: 1.8604x; 1.8604x over previous
#include <cuda_runtime.h>
#include <cuda_fp16.h>
#include <math.h>
#include <stdint.h>

// Problem constants
constexpr int Bc = 4, Lc = 2048, Dc = 512;
constexpr int MR = Bc * Lc;       // 8192

// ---------------------------------------------------------------------------
// Device scratch (no allocations allowed)
// ---------------------------------------------------------------------------
__device__ __half g_xh [(size_t)MR * 3072];
__device__ __half g_wqh[(size_t)2048 * 3072];
__device__ __half g_woh[(size_t)1024 * 1024];
__device__ __half g_q  [(size_t)MR * 512];
__device__ __half g_k  [(size_t)MR * 512];
__device__ __half g_v  [(size_t)MR * 1024];
__device__ __half g_attnh[(size_t)MR * Lc];
__device__ float  g_partial[(size_t)MR * 16];
__device__ __half g_oh [(size_t)MR * 1024];
__device__ int    g_cnt0;      // completed gemm0-qk tiles (kernel A)
__device__ int    g_ca[64];    // completed av tiles per m-block (kernel B, ==8)

// ---------------------------------------------------------------------------
// PTX helpers
// ---------------------------------------------------------------------------
__device__ __forceinline__ uint32_t smem_u32(const void* p) {
    uint32_t a;
    asm("{ .reg .u64 t; cvta.to.shared.u64 t, %1; cvt.u32.u64 %0, t; }" : "=r"(a) : "l"(p));
    return a;
}
__device__ __forceinline__ void cp_async16(uint32_t saddr, const void* gaddr) {
    asm volatile("cp.async.cg.shared.global [%0], [%1], 16;" :: "r"(saddr), "l"(gaddr));
}
#define CP_COMMIT() asm volatile("cp.async.commit_group;" ::: "memory")
#define CP_WAIT(N)  asm volatile("cp.async.wait_group %0;" :: "n"(N) : "memory")

__device__ __forceinline__ void ldm_x4(uint32_t* r, uint32_t addr) {
    asm volatile("ldmatrix.sync.aligned.m8n8.x4.shared.b16 {%0,%1,%2,%3}, [%4];"
                 : "=r"(r[0]), "=r"(r[1]), "=r"(r[2]), "=r"(r[3]) : "r"(addr));
}
__device__ __forceinline__ void ldm_x4_trans(uint32_t* r, uint32_t addr) {
    asm volatile("ldmatrix.sync.aligned.m8n8.x4.trans.shared.b16 {%0,%1,%2,%3}, [%4];"
                 : "=r"(r[0]), "=r"(r[1]), "=r"(r[2]), "=r"(r[3]) : "r"(addr));
}
__device__ __forceinline__ void mma16816(float* c, const uint32_t* a,
                                         uint32_t b0, uint32_t b1) {
    asm volatile(
        "mma.sync.aligned.m16n8k16.row.col.f32.f16.f16.f32 "
        "{%0,%1,%2,%3}, {%4,%5,%6,%7}, {%8,%9}, {%0,%1,%2,%3};"
        : "+f"(c[0]), "+f"(c[1]), "+f"(c[2]), "+f"(c[3])
        : "r"(a[0]), "r"(a[1]), "r"(a[2]), "r"(a[3]), "r"(b0), "r"(b1));
}

// ---------------------------------------------------------------------------
// Tiling constants
// ---------------------------------------------------------------------------
constexpr int ROWH = 72;
constexpr int VROW = 136;
constexpr int OP_TILE = 128 * ROWH * 2;       // 18432 B
constexpr int STAGE = 2 * OP_TILE;            // 36864 B
constexpr int SMEM_TOTAL = 2 * STAGE;         // 73728 B

// ---------------------------------------------------------------------------
// Kernel A: gemm0-qk (bid 0..511) + gemm0-v (512..1023) + gemm1 (1024..2047).
// gemm1 waiters depend ONLY on bids 0..511 (all wave-1 resident) — safe.
// ---------------------------------------------------------------------------
__global__ void __launch_bounds__(128, 3) k_fused01(const float* __restrict__ bqkv,
                                                    const int* __restrict__ pad)
{
    extern __shared__ char smem[];
    const uint32_t sb = smem_u32(smem);
    const int tid = threadIdx.x, wid = tid >> 5, lane = tid & 31;
    const int wm = wid & 1, wn = wid >> 1;

    const int bid = blockIdx.x;
    const int job = (bid < 512) ? 0 : (bid < 1024 ? 1 : 2);  // qk, v, scores
    const __half* A; const __half* B; int K, lda, ldb, bm, bn, bz, xt;
    if (job == 0) {
        bn = (bid & 7) * 128; bm = (bid >> 3) * 128; bz = 0; xt = 0;
        A = g_xh; B = g_wqh; K = 3072; lda = 3072; ldb = 3072;
    } else if (job == 1) {
        const int b = bid - 512;
        bn = 1024 + (b & 7) * 128; bm = (b >> 3) * 128; bz = 0; xt = 0;
        A = g_xh; B = g_wqh; K = 3072; lda = 3072; ldb = 3072;
    } else {
        const int b = bid - 1024;
        bz = b >> 8; const int r = b & 255;
        xt = r & 15; bn = xt * 128; bm = (r >> 4) * 128;
        A = g_q + (size_t)bz * 2048 * 512; B = g_k + (size_t)bz * 2048 * 512;
        K = 512; lda = 512; ldb = 512;
        if (tid == 0) {
            while (atomicAdd(&g_cnt0, 0) < 512) __nanosleep(200);
        }
        __syncthreads();
        __threadfence();
    }

    auto load_tile = [&](int s, int k0) {
        const uint32_t base = sb + s * STAGE;
#pragma unroll
        for (int i = 0; i < 8; i++) {
            const int j = tid + i * 128;
            const int r = j >> 3, c = (j & 7) * 8;
            const uint32_t off = (r * ROWH + c) * 2;
            cp_async16(base + off,           A + (size_t)(bm + r) * lda + k0 + c);
            cp_async16(base + OP_TILE + off, B + (size_t)(bn + r) * ldb + k0 + c);
        }
    };

    float acc[4][8][4] = {};
    uint32_t fa[2][4][4], fb[2][4][4];

    const int ar = wm * 64 + (lane & 15);
    const int br = wn * 64 + (lane & 7) + ((lane >> 4) << 3);
    const int acolo = (lane >> 4) * 8;
    const int bcolo = ((lane >> 3) & 1) * 8;

    load_tile(0, 0);
    CP_COMMIT();

    const int NC = K >> 6;
    for (int ct = 0; ct < NC; ct++) {
        if (ct + 1 < NC) { load_tile((ct + 1) & 1, (ct + 1) * 64); CP_COMMIT(); CP_WAIT(1); }
        else             { CP_WAIT(0); }
        __syncthreads();

        const uint32_t as = sb + (ct & 1) * STAGE;
        const uint32_t bs = as + OP_TILE;

        auto ldfrag = [&](int buf, int ks) {
            const int acol = ks * 16 + acolo;
            const int bcol = ks * 16 + bcolo;
#pragma unroll
            for (int mt = 0; mt < 4; mt++)
                ldm_x4(fa[buf][mt], as + ((ar + mt * 16) * ROWH + acol) * 2);
#pragma unroll
            for (int np = 0; np < 4; np++)
                ldm_x4(fb[buf][np], bs + ((br + np * 16) * ROWH + bcol) * 2);
        };

        ldfrag(0, 0);
#pragma unroll
        for (int ks = 0; ks < 4; ks++) {
            if (ks < 3) ldfrag((ks + 1) & 1, ks + 1);
            const int cb = ks & 1;
#pragma unroll
            for (int mt = 0; mt < 4; mt++)
#pragma unroll
                for (int nt = 0; nt < 8; nt++)
                    mma16816(acc[mt][nt], fa[cb][mt],
                             fb[cb][nt >> 1][(nt & 1) * 2],
                             fb[cb][nt >> 1][(nt & 1) * 2 + 1]);
        }
        __syncthreads();
    }

    const int g = lane >> 2, cc = lane & 3;

    if (job == 0) {
#pragma unroll
        for (int mt = 0; mt < 4; mt++) {
#pragma unroll
            for (int nt = 0; nt < 8; nt++) {
                const int n = bn + wn * 64 + nt * 8 + cc * 2;
                const int m1 = bm + wm * 64 + mt * 16 + g;
                const int m2 = m1 + 8;
                const float* v = acc[mt][nt];
                const int jb = n + (n >= 512 ? 512 : 0);
                const float b0 = bqkv[jb], b1 = bqkv[jb + 1];
                __half* d1; __half* d2;
                if (n < 512) { d1 = g_q + (size_t)m1*512 + n;     d2 = g_q + (size_t)m2*512 + n; }
                else         { d1 = g_k + (size_t)m1*512 + n-512; d2 = g_k + (size_t)m2*512 + n-512; }
                *(__half2*)d1 = __floats2half2_rn(v[0] + b0, v[1] + b1);
                *(__half2*)d2 = __floats2half2_rn(v[2] + b0, v[3] + b1);
            }
        }
        __threadfence();
        __syncthreads();
        if (tid == 0) atomicAdd(&g_cnt0, 1);
        return;
    }
    if (job == 1) {
#pragma unroll
        for (int mt = 0; mt < 4; mt++) {
#pragma unroll
            for (int nt = 0; nt < 8; nt++) {
                const int n = bn + wn * 64 + nt * 8 + cc * 2;
                const int m1 = bm + wm * 64 + mt * 16 + g;
                const int m2 = m1 + 8;
                const float* v = acc[mt][nt];
                const float b0 = bqkv[n + 1024], b1 = bqkv[n + 1025];
                __half* d1 = g_v + (size_t)m1 * 1024 + n - 1024;
                __half* d2 = g_v + (size_t)m2 * 1024 + n - 1024;
                *(__half2*)d1 = __floats2half2_rn(v[0] + b0, v[1] + b1);
                *(__half2*)d2 = __floats2half2_rn(v[2] + b0, v[3] + b1);
            }
        }
        return;
    }

    // scores: scale -> mask -> exp -> fp16 (unnormalized) + partial row sums
    __shared__ float psum[2][128];
    const float scale = 0.04419417382415922f;
    int2 pmv[8];
#pragma unroll
    for (int nt = 0; nt < 8; nt++)
        pmv[nt] = *(const int2*)(pad + (size_t)bz * 2048 + bn + wn * 64 + nt * 8 + cc * 2);

    float rs[4][2] = {};
#pragma unroll
    for (int mt = 0; mt < 4; mt++) {
#pragma unroll
        for (int nt = 0; nt < 8; nt++) {
            const int n = bn + wn * 64 + nt * 8 + cc * 2;
            const int m1 = bm + wm * 64 + mt * 16 + g;
            const int m2 = m1 + 8;
            const float* v = acc[mt][nt];
            const float p0 = pmv[nt].x ? 0.f : __expf(v[0] * scale);
            const float p1 = pmv[nt].y ? 0.f : __expf(v[1] * scale);
            const float p2 = pmv[nt].x ? 0.f : __expf(v[2] * scale);
            const float p3 = pmv[nt].y ? 0.f : __expf(v[3] * scale);
            __half* d1 = g_attnh + (size_t)(bz*2048 + m1) * 2048 + n;
            __half* d2 = g_attnh + (size_t)(bz*2048 + m2) * 2048 + n;
            *(__half2*)d1 = __floats2half2_rn(p0, p1);
            *(__half2*)d2 = __floats2half2_rn(p2, p3);
            rs[mt][0] += p0 + p1;
            rs[mt][1] += p2 + p3;
        }
    }
#pragma unroll
    for (int mt = 0; mt < 4; mt++) {
        rs[mt][0] += __shfl_xor_sync(0xFFFFFFFF, rs[mt][0], 1);
        rs[mt][0] += __shfl_xor_sync(0xFFFFFFFF, rs[mt][0], 2);
        rs[mt][1] += __shfl_xor_sync(0xFFFFFFFF, rs[mt][1], 1);
        rs[mt][1] += __shfl_xor_sync(0xFFFFFFFF, rs[mt][1], 2);
        if (cc == 0) {
            psum[wn][wm * 64 + mt * 16 + g]     = rs[mt][0];
            psum[wn][wm * 64 + mt * 16 + g + 8] = rs[mt][1];
        }
    }
    __syncthreads();
    if (tid < 128)
        g_partial[((size_t)bz * 2048 + bm + tid) * 16 + xt] =
            psum[0][tid] + psum[1][tid];
}

// ---------------------------------------------------------------------------
// Kernel B: av (bid 0..511, inline rowsum + normalize) + out proj (512..1023,
// waits on g_ca[m-block]==8). Grid of 1024 <= one wave (1332 slots) — safe.
// ---------------------------------------------------------------------------
__global__ void __launch_bounds__(128, 3) k_fused23(const float* __restrict__ bout,
                                                    float* __restrict__ outf)
{
    extern __shared__ char smem[];
    const uint32_t sb = smem_u32(smem);
    const int tid = threadIdx.x, wid = tid >> 5, lane = tid & 31;
    const int wm = wid & 1, wn = wid >> 1;

    const int bid = blockIdx.x;
    const bool isAV = bid < 512;
    const __half* A; const __half* B; int K, lda, ldb, bm, bn, bz = 0;
    if (isAV) {
        bz = bid >> 7; const int r = bid & 127;
        bm = (r >> 3) * 128; bn = (r & 7) * 128;
        A = g_attnh + (size_t)bz * 2048 * 2048; B = g_v + (size_t)bz * 2048 * 1024;
        K = 2048; lda = 2048; ldb = 1024;
    } else {
        const int b = bid - 512;
        const int bm64 = b >> 3;
        bm = bm64 * 128; bn = (b & 7) * 128;
        A = g_oh; B = g_woh; K = 1024; lda = 1024; ldb = 1024;
        if (tid == 0) {
            while (atomicAdd(&g_ca[bm64], 0) < 8) __nanosleep(200);
        }
        __syncthreads();
        __threadfence();
    }

    auto load_tile = [&](int s, int k0) {
        const uint32_t base = sb + s * STAGE;
#pragma unroll
        for (int i = 0; i < 8; i++) {
            const int j = tid + i * 128;
            const int r = j >> 3, c = (j & 7) * 8;
            cp_async16(base + (r * ROWH + c) * 2,
                       A + (size_t)(bm + r) * lda + k0 + c);
            if (isAV) {
                const int rv = j >> 4, cv = (j & 15) * 8;
                cp_async16(base + OP_TILE + (rv * VROW + cv) * 2,
                           B + (size_t)(k0 + rv) * ldb + bn + cv);
            } else {
                cp_async16(base + OP_TILE + (r * ROWH + c) * 2,
                           B + (size_t)(bn + r) * ldb + k0 + c);
            }
        }
    };

    float acc[4][8][4] = {};
    uint32_t fa[2][4][4], fb[2][4][4];

    const int ar = wm * 64 + (lane & 15);
    const int br = wn * 64 + (lane & 7) + ((lane >> 4) << 3);
    const int acolo = (lane >> 4) * 8;
    const int bcolo = ((lane >> 3) & 1) * 8;
    const int bk_l = ((lane >> 3) & 1) * 8 + (lane & 7);
    const int bn_l = ((lane >> 4) & 1) * 8;

    load_tile(0, 0);
    CP_COMMIT();

    const int NC = K >> 6;
    for (int ct = 0; ct < NC; ct++) {
        if (ct + 1 < NC) { load_tile((ct + 1) & 1, (ct + 1) * 64); CP_COMMIT(); CP_WAIT(1); }
        else             { CP_WAIT(0); }
        __syncthreads();

        const uint32_t as = sb + (ct & 1) * STAGE;
        const uint32_t bs = as + OP_TILE;

        auto ldfrag = [&](int buf, int ks) {
            const int acol = ks * 16 + acolo;
#pragma unroll
            for (int mt = 0; mt < 4; mt++)
                ldm_x4(fa[buf][mt], as + ((ar + mt * 16) * ROWH + acol) * 2);
            if (isAV) {
                const int krow = ks * 16 + bk_l;
#pragma unroll
                for (int np = 0; np < 4; np++)
                    ldm_x4_trans(fb[buf][np],
                        bs + (krow * VROW + wn * 64 + np * 16 + bn_l) * 2);
            } else {
                const int bcol = ks * 16 + bcolo;
#pragma unroll
                for (int np = 0; np < 4; np++)
                    ldm_x4(fb[buf][np], bs + ((br + np * 16) * ROWH + bcol) * 2);
            }
        };

        ldfrag(0, 0);
#pragma unroll
        for (int ks = 0; ks < 4; ks++) {
            if (ks < 3) ldfrag((ks + 1) & 1, ks + 1);
            const int cb = ks & 1;
#pragma unroll
            for (int mt = 0; mt < 4; mt++)
#pragma unroll
                for (int nt = 0; nt < 8; nt++)
                    mma16816(acc[mt][nt], fa[cb][mt],
                             fb[cb][nt >> 1][(nt & 1) * 2],
                             fb[cb][nt >> 1][(nt & 1) * 2 + 1]);
        }
        __syncthreads();
    }

    const int g = lane >> 2, cc = lane & 3;

    if (isAV) {
        // inline rowsum -> normalize -> g_oh
        float* sinv = (float*)smem;          // reuse tile smem (post-mainloop)
        if (tid < 128) {
            const float4* p = (const float4*)(g_partial + ((size_t)bz * 2048 + bm + tid) * 16);
            float4 a = p[0], b = p[1], c = p[2], d = p[3];
            const float s = ((a.x + a.y) + (a.z + a.w)) + ((b.x + b.y) + (b.z + b.w))
                          + ((c.x + c.y) + (c.z + c.w)) + ((d.x + d.y) + (d.z + d.w));
            sinv[tid] = 1.f / s;
        }
        __syncthreads();
#pragma unroll
        for (int mt = 0; mt < 4; mt++) {
#pragma unroll
            for (int nt = 0; nt < 8; nt++) {
                const int n = bn + wn * 64 + nt * 8 + cc * 2;
                const int l1 = wm * 64 + mt * 16 + g;
                const int m1 = bm + l1, m2 = m1 + 8;
                const float* v = acc[mt][nt];
                const float inv1 = sinv[l1], inv2 = sinv[l1 + 8];
                __half* d1 = g_oh + (size_t)(bz*2048 + m1) * 1024 + n;
                __half* d2 = g_oh + (size_t)(bz*2048 + m2) * 1024 + n;
                *(__half2*)d1 = __floats2half2_rn(v[0] * inv1, v[1] * inv1);
                *(__half2*)d2 = __floats2half2_rn(v[2] * inv2, v[3] * inv2);
            }
        }
        __threadfence();
        __syncthreads();
        if (tid == 0) atomicAdd(&g_ca[bz * 16 + (bm >> 7)], 1);
        return;
    }

    // out projection
#pragma unroll
    for (int mt = 0; mt < 4; mt++) {
#pragma unroll
        for (int nt = 0; nt < 8; nt++) {
            const int n = bn + wn * 64 + nt * 8 + cc * 2;
            const int m1 = bm + wm * 64 + mt * 16 + g;
            const int m2 = m1 + 8;
            const float* v = acc[mt][nt];
            const float b0 = bout[n], b1 = bout[n + 1];
            float* o1; float* o2;
            if (n < 512) { o1 = outf + (size_t)m1*512 + n;       o2 = outf + (size_t)m2*512 + n; }
            else         { o1 = outf + (size_t)MR*512 + (size_t)m1*512 + n-512;
                           o2 = outf + (size_t)MR*512 + (size_t)m2*512 + n-512; }
            *(float2*)o1 = make_float2(v[0] + b0, v[1] + b1);
            *(float2*)o2 = make_float2(v[2] + b0, v[3] + b1);
        }
    }
}

// ---------------------------------------------------------------------------
// Conversions (+ counter reset)
// ---------------------------------------------------------------------------
__global__ void __launch_bounds__(256) k_conv_x(
    const float* __restrict__ i0, const float* __restrict__ i1,
    const float* __restrict__ i2, const float* __restrict__ i3,
    const float* __restrict__ i4, const float* __restrict__ i5)
{
    const int m = blockIdx.x, t = threadIdx.x;
    if (m == 0) {
        if (t == 0) g_cnt0 = 0;
        if (t >= 32 && t < 96) g_ca[t - 32] = 0;
    }
    const float* ins[6] = {i0, i1, i2, i3, i4, i5};
    __half2* out = (__half2*)(g_xh + (size_t)m * 3072);
#pragma unroll
    for (int i = 0; i < 6; i++) {
        float2 v = ((const float2*)(ins[i] + (size_t)m * 512))[t];
        out[i * 256 + t] = __floats2half2_rn(v.x, v.y);
    }
}

__global__ void __launch_bounds__(256) k_conv_wq(const float* __restrict__ W)
{
    const int n = blockIdx.x, t = threadIdx.x;
    const int wrow = n + (n >= 512 ? 512 : 0) + (n >= 1024 ? 512 : 0);
    const float2* src = (const float2*)(W + (size_t)wrow * 3072);
    __half2* dst = (__half2*)(g_wqh + (size_t)n * 3072);
#pragma unroll
    for (int i = 0; i < 6; i++) {
        float2 v = src[t + i * 256];
        dst[t + i * 256] = __floats2half2_rn(v.x, v.y);
    }
}

__global__ void __launch_bounds__(256) k_conv_wo(const float* __restrict__ W)
{
    const int n = blockIdx.x, t = threadIdx.x;
    const float2* src = (const float2*)(W + (size_t)n * 1024);
    __half2* dst = (__half2*)(g_woh + (size_t)n * 1024);
#pragma unroll
    for (int i = 0; i < 2; i++) {
        float2 v = src[t + i * 256];
        dst[t + i * 256] = __floats2half2_rn(v.x, v.y);
    }
}

// ---------------------------------------------------------------------------
extern "C" void kernel_launch(void* const* d_in, const int* in_sizes, int n_in,
                              void* d_out, int out_size)
{
    const float* q_r = (const float*)d_in[0];
    const float* q_i = (const float*)d_in[1];
    const float* k_r = (const float*)d_in[2];
    const float* k_i = (const float*)d_in[3];
    const float* v_r = (const float*)d_in[4];
    const float* v_i = (const float*)d_in[5];
    const int* pad   = (const int*)d_in[6];
    const float* Wqkv = (const float*)d_in[7];
    const float* bqkv = (const float*)d_in[8];
    const float* Wout = (const float*)d_in[9];
    const float* bout = (const float*)d_in[10];
    float* out = (float*)d_out;

    cudaFuncSetAttribute(k_fused01, cudaFuncAttributeMaxDynamicSharedMemorySize, SMEM_TOTAL);
    cudaFuncSetAttribute(k_fused23, cudaFuncAttributeMaxDynamicSharedMemorySize, SMEM_TOTAL);

    k_conv_x<<<MR, 256>>>(q_r, q_i, k_r, k_i, v_r, v_i);
    k_conv_wq<<<2048, 256>>>(Wqkv);
    k_conv_wo<<<1024, 256>>>(Wout);

    k_fused01<<<2048, 128, SMEM_TOTAL>>>(bqkv, pad);   // gemm0 + gemm1
    k_fused23<<<1024, 128, SMEM_TOTAL>>>(bout, out);   // attn@V + out proj
}

// round 14
// speedup vs baseline: 3.5204x; 1.8923x over previous
#include <cuda_runtime.h>
#include <cuda_fp16.h>
#include <math.h>
#include <stdint.h>

// Problem constants
constexpr int Bc = 4, Lc = 2048, Dc = 512;
constexpr int MR = Bc * Lc;       // 8192

// ---------------------------------------------------------------------------
// Device scratch (no allocations allowed)
// ---------------------------------------------------------------------------
__device__ __half g_xh [(size_t)MR * 3072];
__device__ __half g_wqh[(size_t)2048 * 3072];
__device__ __half g_woh[(size_t)1024 * 1024];
__device__ __half g_q  [(size_t)MR * 512];
__device__ __half g_k  [(size_t)MR * 512];
__device__ __half g_v  [(size_t)MR * 1024];
__device__ __half g_attnh[(size_t)MR * Lc];
__device__ float  g_partial[(size_t)MR * 16];
__device__ __half g_oh [(size_t)MR * 1024];
__device__ int    g_cnt0;      // completed gemm0-qk tiles

// ---------------------------------------------------------------------------
// PTX helpers
// ---------------------------------------------------------------------------
__device__ __forceinline__ uint32_t smem_u32(const void* p) {
    uint32_t a;
    asm("{ .reg .u64 t; cvta.to.shared.u64 t, %1; cvt.u32.u64 %0, t; }" : "=r"(a) : "l"(p));
    return a;
}
__device__ __forceinline__ void cp_async16(uint32_t saddr, const void* gaddr) {
    asm volatile("cp.async.cg.shared.global [%0], [%1], 16;" :: "r"(saddr), "l"(gaddr));
}
#define CP_COMMIT() asm volatile("cp.async.commit_group;" ::: "memory")
#define CP_WAIT(N)  asm volatile("cp.async.wait_group %0;" :: "n"(N) : "memory")

__device__ __forceinline__ void ldm_x4(uint32_t* r, uint32_t addr) {
    asm volatile("ldmatrix.sync.aligned.m8n8.x4.shared.b16 {%0,%1,%2,%3}, [%4];"
                 : "=r"(r[0]), "=r"(r[1]), "=r"(r[2]), "=r"(r[3]) : "r"(addr));
}
__device__ __forceinline__ void ldm_x4_trans(uint32_t* r, uint32_t addr) {
    asm volatile("ldmatrix.sync.aligned.m8n8.x4.trans.shared.b16 {%0,%1,%2,%3}, [%4];"
                 : "=r"(r[0]), "=r"(r[1]), "=r"(r[2]), "=r"(r[3]) : "r"(addr));
}
__device__ __forceinline__ void mma16816(float* c, const uint32_t* a,
                                         uint32_t b0, uint32_t b1) {
    asm volatile(
        "mma.sync.aligned.m16n8k16.row.col.f32.f16.f16.f32 "
        "{%0,%1,%2,%3}, {%4,%5,%6,%7}, {%8,%9}, {%0,%1,%2,%3};"
        : "+f"(c[0]), "+f"(c[1]), "+f"(c[2]), "+f"(c[3])
        : "r"(a[0]), "r"(a[1]), "r"(a[2]), "r"(a[3]), "r"(b0), "r"(b1));
}

// ---------------------------------------------------------------------------
// Tiling constants
// ---------------------------------------------------------------------------
constexpr int ROWH = 72;
constexpr int VROW = 136;
constexpr int OP_TILE = 128 * ROWH * 2;       // 18432 B
constexpr int STAGE = 2 * OP_TILE;            // 36864 B
constexpr int SMEM_TOTAL = 2 * STAGE;         // 73728 B

// ---------------------------------------------------------------------------
// Kernel A: gemm0-qk (bid 0..511) + gemm0-v (512..1023) + gemm1 (1024..2047).
// gemm1 waiters depend only on bids 0..511 (dispatched strictly earlier) —
// validated stable in R11.
// ---------------------------------------------------------------------------
__global__ void __launch_bounds__(128, 3) k_fused01(const float* __restrict__ bqkv,
                                                    const int* __restrict__ pad)
{
    extern __shared__ char smem[];
    const uint32_t sb = smem_u32(smem);
    const int tid = threadIdx.x, wid = tid >> 5, lane = tid & 31;
    const int wm = wid & 1, wn = wid >> 1;

    const int bid = blockIdx.x;
    const int job = (bid < 512) ? 0 : (bid < 1024 ? 1 : 2);  // qk, v, scores
    const __half* A; const __half* B; int K, lda, ldb, bm, bn, bz, xt;
    if (job == 0) {
        bn = (bid & 7) * 128; bm = (bid >> 3) * 128; bz = 0; xt = 0;
        A = g_xh; B = g_wqh; K = 3072; lda = 3072; ldb = 3072;
    } else if (job == 1) {
        const int b = bid - 512;
        bn = 1024 + (b & 7) * 128; bm = (b >> 3) * 128; bz = 0; xt = 0;
        A = g_xh; B = g_wqh; K = 3072; lda = 3072; ldb = 3072;
    } else {
        const int b = bid - 1024;
        bz = b >> 8; const int r = b & 255;
        xt = r & 15; bn = xt * 128; bm = (r >> 4) * 128;
        A = g_q + (size_t)bz * 2048 * 512; B = g_k + (size_t)bz * 2048 * 512;
        K = 512; lda = 512; ldb = 512;
        if (tid == 0) {
            while (atomicAdd(&g_cnt0, 0) < 512) __nanosleep(200);
        }
        __syncthreads();
        __threadfence();
    }

    auto load_tile = [&](int s, int k0) {
        const uint32_t base = sb + s * STAGE;
#pragma unroll
        for (int i = 0; i < 8; i++) {
            const int j = tid + i * 128;
            const int r = j >> 3, c = (j & 7) * 8;
            const uint32_t off = (r * ROWH + c) * 2;
            cp_async16(base + off,           A + (size_t)(bm + r) * lda + k0 + c);
            cp_async16(base + OP_TILE + off, B + (size_t)(bn + r) * ldb + k0 + c);
        }
    };

    float acc[4][8][4] = {};
    uint32_t fa[2][4][4], fb[2][4][4];

    const int ar = wm * 64 + (lane & 15);
    const int br = wn * 64 + (lane & 7) + ((lane >> 4) << 3);
    const int acolo = (lane >> 4) * 8;
    const int bcolo = ((lane >> 3) & 1) * 8;

    load_tile(0, 0);
    CP_COMMIT();

    const int NC = K >> 6;
    for (int ct = 0; ct < NC; ct++) {
        if (ct + 1 < NC) { load_tile((ct + 1) & 1, (ct + 1) * 64); CP_COMMIT(); CP_WAIT(1); }
        else             { CP_WAIT(0); }
        __syncthreads();

        const uint32_t as = sb + (ct & 1) * STAGE;
        const uint32_t bs = as + OP_TILE;

        auto ldfrag = [&](int buf, int ks) {
            const int acol = ks * 16 + acolo;
            const int bcol = ks * 16 + bcolo;
#pragma unroll
            for (int mt = 0; mt < 4; mt++)
                ldm_x4(fa[buf][mt], as + ((ar + mt * 16) * ROWH + acol) * 2);
#pragma unroll
            for (int np = 0; np < 4; np++)
                ldm_x4(fb[buf][np], bs + ((br + np * 16) * ROWH + bcol) * 2);
        };

        ldfrag(0, 0);
#pragma unroll
        for (int ks = 0; ks < 4; ks++) {
            if (ks < 3) ldfrag((ks + 1) & 1, ks + 1);
            const int cb = ks & 1;
#pragma unroll
            for (int mt = 0; mt < 4; mt++)
#pragma unroll
                for (int nt = 0; nt < 8; nt++)
                    mma16816(acc[mt][nt], fa[cb][mt],
                             fb[cb][nt >> 1][(nt & 1) * 2],
                             fb[cb][nt >> 1][(nt & 1) * 2 + 1]);
        }
        __syncthreads();
    }

    const int g = lane >> 2, cc = lane & 3;

    if (job == 0) {
#pragma unroll
        for (int mt = 0; mt < 4; mt++) {
#pragma unroll
            for (int nt = 0; nt < 8; nt++) {
                const int n = bn + wn * 64 + nt * 8 + cc * 2;
                const int m1 = bm + wm * 64 + mt * 16 + g;
                const int m2 = m1 + 8;
                const float* v = acc[mt][nt];
                const int jb = n + (n >= 512 ? 512 : 0);
                const float b0 = bqkv[jb], b1 = bqkv[jb + 1];
                __half* d1; __half* d2;
                if (n < 512) { d1 = g_q + (size_t)m1*512 + n;     d2 = g_q + (size_t)m2*512 + n; }
                else         { d1 = g_k + (size_t)m1*512 + n-512; d2 = g_k + (size_t)m2*512 + n-512; }
                *(__half2*)d1 = __floats2half2_rn(v[0] + b0, v[1] + b1);
                *(__half2*)d2 = __floats2half2_rn(v[2] + b0, v[3] + b1);
            }
        }
        __threadfence();
        __syncthreads();
        if (tid == 0) atomicAdd(&g_cnt0, 1);
        return;
    }
    if (job == 1) {
#pragma unroll
        for (int mt = 0; mt < 4; mt++) {
#pragma unroll
            for (int nt = 0; nt < 8; nt++) {
                const int n = bn + wn * 64 + nt * 8 + cc * 2;
                const int m1 = bm + wm * 64 + mt * 16 + g;
                const int m2 = m1 + 8;
                const float* v = acc[mt][nt];
                const float b0 = bqkv[n + 1024], b1 = bqkv[n + 1025];
                __half* d1 = g_v + (size_t)m1 * 1024 + n - 1024;
                __half* d2 = g_v + (size_t)m2 * 1024 + n - 1024;
                *(__half2*)d1 = __floats2half2_rn(v[0] + b0, v[1] + b1);
                *(__half2*)d2 = __floats2half2_rn(v[2] + b0, v[3] + b1);
            }
        }
        return;
    }

    // scores: scale -> mask -> exp -> fp16 (unnormalized) + partial row sums
    __shared__ float psum[2][128];
    const float scale = 0.04419417382415922f;
    int2 pmv[8];
#pragma unroll
    for (int nt = 0; nt < 8; nt++)
        pmv[nt] = *(const int2*)(pad + (size_t)bz * 2048 + bn + wn * 64 + nt * 8 + cc * 2);

    float rs[4][2] = {};
#pragma unroll
    for (int mt = 0; mt < 4; mt++) {
#pragma unroll
        for (int nt = 0; nt < 8; nt++) {
            const int n = bn + wn * 64 + nt * 8 + cc * 2;
            const int m1 = bm + wm * 64 + mt * 16 + g;
            const int m2 = m1 + 8;
            const float* v = acc[mt][nt];
            const float p0 = pmv[nt].x ? 0.f : __expf(v[0] * scale);
            const float p1 = pmv[nt].y ? 0.f : __expf(v[1] * scale);
            const float p2 = pmv[nt].x ? 0.f : __expf(v[2] * scale);
            const float p3 = pmv[nt].y ? 0.f : __expf(v[3] * scale);
            __half* d1 = g_attnh + (size_t)(bz*2048 + m1) * 2048 + n;
            __half* d2 = g_attnh + (size_t)(bz*2048 + m2) * 2048 + n;
            *(__half2*)d1 = __floats2half2_rn(p0, p1);
            *(__half2*)d2 = __floats2half2_rn(p2, p3);
            rs[mt][0] += p0 + p1;
            rs[mt][1] += p2 + p3;
        }
    }
#pragma unroll
    for (int mt = 0; mt < 4; mt++) {
        rs[mt][0] += __shfl_xor_sync(0xFFFFFFFF, rs[mt][0], 1);
        rs[mt][0] += __shfl_xor_sync(0xFFFFFFFF, rs[mt][0], 2);
        rs[mt][1] += __shfl_xor_sync(0xFFFFFFFF, rs[mt][1], 1);
        rs[mt][1] += __shfl_xor_sync(0xFFFFFFFF, rs[mt][1], 2);
        if (cc == 0) {
            psum[wn][wm * 64 + mt * 16 + g]     = rs[mt][0];
            psum[wn][wm * 64 + mt * 16 + g + 8] = rs[mt][1];
        }
    }
    __syncthreads();
    if (tid < 128)
        g_partial[((size_t)bz * 2048 + bm + tid) * 16 + xt] =
            psum[0][tid] + psum[1][tid];
}

// ---------------------------------------------------------------------------
// Template GEMM: EPI 2 = attn@V (trans-B, inline rowsum + normalize),
//                EPI 3 = out projection. No cross-CTA waits.
// ---------------------------------------------------------------------------
template <int EPI>
__global__ void __launch_bounds__(128, 3) gemm_nt(const float* __restrict__ bias,
                                                  float* __restrict__ outf)
{
    extern __shared__ char smem[];
    const uint32_t sb = smem_u32(smem);
    const int tid = threadIdx.x, wid = tid >> 5, lane = tid & 31;
    const int wm = wid & 1, wn = wid >> 1;
    const int bz = blockIdx.z;
    const int bm = blockIdx.y * 128, bn = blockIdx.x * 128;

    const __half* A; const __half* B; int K, lda, ldb;
    if constexpr (EPI == 2) { A = g_attnh + (size_t)bz*2048*2048; B = g_v + (size_t)bz*2048*1024; K = 2048; lda = 2048; ldb = 1024; }
    if constexpr (EPI == 3) { A = g_oh;  B = g_woh; K = 1024; lda = 1024; ldb = 1024; }

    auto load_tile = [&](int s, int k0) {
        const uint32_t base = sb + s * STAGE;
#pragma unroll
        for (int i = 0; i < 8; i++) {
            const int j = tid + i * 128;
            const int r = j >> 3, c = (j & 7) * 8;
            cp_async16(base + (r * ROWH + c) * 2,
                       A + (size_t)(bm + r) * lda + k0 + c);
            if constexpr (EPI == 2) {
                const int rv = j >> 4, cv = (j & 15) * 8;
                cp_async16(base + OP_TILE + (rv * VROW + cv) * 2,
                           B + (size_t)(k0 + rv) * ldb + bn + cv);
            } else {
                cp_async16(base + OP_TILE + (r * ROWH + c) * 2,
                           B + (size_t)(bn + r) * ldb + k0 + c);
            }
        }
    };

    float acc[4][8][4] = {};
    uint32_t fa[2][4][4], fb[2][4][4];

    const int ar = wm * 64 + (lane & 15);
    const int br = wn * 64 + (lane & 7) + ((lane >> 4) << 3);
    const int acolo = (lane >> 4) * 8;
    const int bcolo = ((lane >> 3) & 1) * 8;
    const int bk_l = ((lane >> 3) & 1) * 8 + (lane & 7);
    const int bn_l = ((lane >> 4) & 1) * 8;

    load_tile(0, 0);
    CP_COMMIT();

    const int NC = K >> 6;
    for (int ct = 0; ct < NC; ct++) {
        if (ct + 1 < NC) { load_tile((ct + 1) & 1, (ct + 1) * 64); CP_COMMIT(); CP_WAIT(1); }
        else             { CP_WAIT(0); }
        __syncthreads();

        const uint32_t as = sb + (ct & 1) * STAGE;
        const uint32_t bs = as + OP_TILE;

        auto ldfrag = [&](int buf, int ks) {
            const int acol = ks * 16 + acolo;
#pragma unroll
            for (int mt = 0; mt < 4; mt++)
                ldm_x4(fa[buf][mt], as + ((ar + mt * 16) * ROWH + acol) * 2);
            if constexpr (EPI == 2) {
                const int krow = ks * 16 + bk_l;
#pragma unroll
                for (int np = 0; np < 4; np++)
                    ldm_x4_trans(fb[buf][np],
                        bs + (krow * VROW + wn * 64 + np * 16 + bn_l) * 2);
            } else {
                const int bcol = ks * 16 + bcolo;
#pragma unroll
                for (int np = 0; np < 4; np++)
                    ldm_x4(fb[buf][np], bs + ((br + np * 16) * ROWH + bcol) * 2);
            }
        };

        ldfrag(0, 0);
#pragma unroll
        for (int ks = 0; ks < 4; ks++) {
            if (ks < 3) ldfrag((ks + 1) & 1, ks + 1);
            const int cb = ks & 1;
#pragma unroll
            for (int mt = 0; mt < 4; mt++)
#pragma unroll
                for (int nt = 0; nt < 8; nt++)
                    mma16816(acc[mt][nt], fa[cb][mt],
                             fb[cb][nt >> 1][(nt & 1) * 2],
                             fb[cb][nt >> 1][(nt & 1) * 2 + 1]);
        }
        __syncthreads();
    }

    const int g = lane >> 2, cc = lane & 3;

    if constexpr (EPI == 2) {
        // inline rowsum -> normalize -> g_oh (reuse tile smem after mainloop)
        float* sinv = (float*)smem;
        if (tid < 128) {
            const float4* p = (const float4*)(g_partial + ((size_t)bz * 2048 + bm + tid) * 16);
            float4 a = p[0], b = p[1], c = p[2], d = p[3];
            const float s = ((a.x + a.y) + (a.z + a.w)) + ((b.x + b.y) + (b.z + b.w))
                          + ((c.x + c.y) + (c.z + c.w)) + ((d.x + d.y) + (d.z + d.w));
            sinv[tid] = 1.f / s;
        }
        __syncthreads();
#pragma unroll
        for (int mt = 0; mt < 4; mt++) {
#pragma unroll
            for (int nt = 0; nt < 8; nt++) {
                const int n = bn + wn * 64 + nt * 8 + cc * 2;
                const int l1 = wm * 64 + mt * 16 + g;
                const int m1 = bm + l1, m2 = m1 + 8;
                const float* v = acc[mt][nt];
                const float inv1 = sinv[l1], inv2 = sinv[l1 + 8];
                __half* d1 = g_oh + (size_t)(bz*2048 + m1) * 1024 + n;
                __half* d2 = g_oh + (size_t)(bz*2048 + m2) * 1024 + n;
                *(__half2*)d1 = __floats2half2_rn(v[0] * inv1, v[1] * inv1);
                *(__half2*)d2 = __floats2half2_rn(v[2] * inv2, v[3] * inv2);
            }
        }
    }
    if constexpr (EPI == 3) {
#pragma unroll
        for (int mt = 0; mt < 4; mt++) {
#pragma unroll
            for (int nt = 0; nt < 8; nt++) {
                const int n = bn + wn * 64 + nt * 8 + cc * 2;
                const int m1 = bm + wm * 64 + mt * 16 + g;
                const int m2 = m1 + 8;
                const float* v = acc[mt][nt];
                const float b0 = bias[n], b1 = bias[n + 1];
                float* o1; float* o2;
                if (n < 512) { o1 = outf + (size_t)m1*512 + n;       o2 = outf + (size_t)m2*512 + n; }
                else         { o1 = outf + (size_t)MR*512 + (size_t)m1*512 + n-512;
                               o2 = outf + (size_t)MR*512 + (size_t)m2*512 + n-512; }
                *(float2*)o1 = make_float2(v[0] + b0, v[1] + b1);
                *(float2*)o2 = make_float2(v[2] + b0, v[3] + b1);
            }
        }
    }
}

// ---------------------------------------------------------------------------
// Conversions (+ counter reset)
// ---------------------------------------------------------------------------
__global__ void __launch_bounds__(256) k_conv_x(
    const float* __restrict__ i0, const float* __restrict__ i1,
    const float* __restrict__ i2, const float* __restrict__ i3,
    const float* __restrict__ i4, const float* __restrict__ i5)
{
    const int m = blockIdx.x, t = threadIdx.x;
    if (m == 0 && t == 0) g_cnt0 = 0;   // reset per replay
    const float* ins[6] = {i0, i1, i2, i3, i4, i5};
    __half2* out = (__half2*)(g_xh + (size_t)m * 3072);
#pragma unroll
    for (int i = 0; i < 6; i++) {
        float2 v = ((const float2*)(ins[i] + (size_t)m * 512))[t];
        out[i * 256 + t] = __floats2half2_rn(v.x, v.y);
    }
}

// merged weight conversions: bid<2048 -> W_qkv (gathered rows), else -> W_out
__global__ void __launch_bounds__(256) k_conv_w(const float* __restrict__ Wq,
                                                const float* __restrict__ Wo)
{
    const int t = threadIdx.x;
    if (blockIdx.x < 2048) {
        const int n = blockIdx.x;
        const int wrow = n + (n >= 512 ? 512 : 0) + (n >= 1024 ? 512 : 0);
        const float2* src = (const float2*)(Wq + (size_t)wrow * 3072);
        __half2* dst = (__half2*)(g_wqh + (size_t)n * 3072);
#pragma unroll
        for (int i = 0; i < 6; i++) {
            float2 v = src[t + i * 256];
            dst[t + i * 256] = __floats2half2_rn(v.x, v.y);
        }
    } else {
        const int n = blockIdx.x - 2048;
        const float2* src = (const float2*)(Wo + (size_t)n * 1024);
        __half2* dst = (__half2*)(g_woh + (size_t)n * 1024);
#pragma unroll
        for (int i = 0; i < 2; i++) {
            float2 v = src[t + i * 256];
            dst[t + i * 256] = __floats2half2_rn(v.x, v.y);
        }
    }
}

// ---------------------------------------------------------------------------
extern "C" void kernel_launch(void* const* d_in, const int* in_sizes, int n_in,
                              void* d_out, int out_size)
{
    const float* q_r = (const float*)d_in[0];
    const float* q_i = (const float*)d_in[1];
    const float* k_r = (const float*)d_in[2];
    const float* k_i = (const float*)d_in[3];
    const float* v_r = (const float*)d_in[4];
    const float* v_i = (const float*)d_in[5];
    const int* pad   = (const int*)d_in[6];
    const float* Wqkv = (const float*)d_in[7];
    const float* bqkv = (const float*)d_in[8];
    const float* Wout = (const float*)d_in[9];
    const float* bout = (const float*)d_in[10];
    float* out = (float*)d_out;

    cudaFuncSetAttribute(k_fused01,  cudaFuncAttributeMaxDynamicSharedMemorySize, SMEM_TOTAL);
    cudaFuncSetAttribute(gemm_nt<2>, cudaFuncAttributeMaxDynamicSharedMemorySize, SMEM_TOTAL);
    cudaFuncSetAttribute(gemm_nt<3>, cudaFuncAttributeMaxDynamicSharedMemorySize, SMEM_TOTAL);

    k_conv_x<<<MR, 256>>>(q_r, q_i, k_r, k_i, v_r, v_i);
    k_conv_w<<<3072, 256>>>(Wqkv, Wout);

    k_fused01<<<2048, 128, SMEM_TOTAL>>>(bqkv, pad);                    // gemm0 + gemm1
    gemm_nt<2><<<dim3(8, 16, 4), 128, SMEM_TOTAL>>>(nullptr, nullptr);  // attn@V (+rowsum)
    gemm_nt<3><<<dim3(8, 64, 1), 128, SMEM_TOTAL>>>(bout, out);         // out proj
}